// round 3
// baseline (speedup 1.0000x reference)
#include <cuda_runtime.h>
#include <math.h>

#define Bn 4
#define Tt 8
#define Cc 64
#define Ff 16
#define Nn 8192
#define HW 1024      // H*W
#define BN (Bn*Nn)   // 32768

// Scratch (device globals: no allocations allowed in kernel_launch)
__device__ __align__(16) float g_pooled[BN];
__device__ __align__(16) float g_v[BN];

// ---------------------------------------------------------------------------
// Kernel 1: pooled[b,n] = mean_f(conv1(x))[b,n,f]  ==  wbar . x[b,:,n] + bbar
// ---------------------------------------------------------------------------
__global__ void __launch_bounds__(256) pooled_kernel(
    const float* __restrict__ x,
    const float* __restrict__ conv1_w,
    const float* __restrict__ conv1_b)
{
    __shared__ float s_wbar[Cc];
    __shared__ float s_bbar;
    int tid = threadIdx.x;
    if (tid < Cc) {
        float s = 0.f;
        #pragma unroll
        for (int f = 0; f < Ff; ++f) s += conv1_w[f * Cc + tid];
        s_wbar[tid] = s * (1.f / Ff);
    }
    if (tid == 0) {
        float s = 0.f;
        #pragma unroll
        for (int f = 0; f < Ff; ++f) s += conv1_b[f];
        s_bbar = s * (1.f / Ff);
    }
    __syncthreads();

    int i  = blockIdx.x * blockDim.x + tid;   // [0, B*N)
    int b  = i >> 13;
    int n  = i & (Nn - 1);
    int t  = n >> 10;
    int hw = n & (HW - 1);
    const float* xp = x + ((b * Tt + t) * Cc) * HW + hw;

    float a0 = 0.f, a1 = 0.f, a2 = 0.f, a3 = 0.f;
    #pragma unroll
    for (int c = 0; c < Cc; c += 4) {
        a0 = fmaf(s_wbar[c + 0], xp[(c + 0) * HW], a0);
        a1 = fmaf(s_wbar[c + 1], xp[(c + 1) * HW], a1);
        a2 = fmaf(s_wbar[c + 2], xp[(c + 2) * HW], a2);
        a3 = fmaf(s_wbar[c + 3], xp[(c + 3) * HW], a3);
    }
    g_pooled[i] = s_bbar + (a0 + a1) + (a2 + a3);
}

// ---------------------------------------------------------------------------
// Kernel 2: v[b,n] = sigmoid(pooled[b,:] . W[n,:] + bias[n])
// Warp handles 4 rows x 4 batches; float4 streaming loads of W (__ldcs).
// HBM-bound: streams the 256MB weight matrix exactly once.
// ---------------------------------------------------------------------------
__global__ void __launch_bounds__(256) gemv_kernel(
    const float* __restrict__ Wm,
    const float* __restrict__ bias)
{
    int warp = threadIdx.x >> 5;
    int lane = threadIdx.x & 31;
    int n0 = (blockIdx.x * 8 + warp) * 4;   // first of 4 rows

    const float4* Wv = (const float4*)Wm;
    const float4* Pv = (const float4*)g_pooled;
    const int K4 = Nn / 4;   // 2048 float4 per row

    float acc[4][4];
    #pragma unroll
    for (int b = 0; b < 4; ++b)
        #pragma unroll
        for (int r = 0; r < 4; ++r) acc[b][r] = 0.f;

    #pragma unroll 2
    for (int k4 = lane; k4 < K4; k4 += 32) {
        float4 p[4];
        #pragma unroll
        for (int b = 0; b < 4; ++b) p[b] = __ldg(Pv + b * K4 + k4);
        #pragma unroll
        for (int r = 0; r < 4; ++r) {
            float4 w = __ldcs(Wv + (n0 + r) * K4 + k4);
            #pragma unroll
            for (int b = 0; b < 4; ++b) {
                acc[b][r] = fmaf(p[b].x, w.x, acc[b][r]);
                acc[b][r] = fmaf(p[b].y, w.y, acc[b][r]);
                acc[b][r] = fmaf(p[b].z, w.z, acc[b][r]);
                acc[b][r] = fmaf(p[b].w, w.w, acc[b][r]);
            }
        }
    }

    // Warp-wide butterfly reduce each of the 16 accumulators
    #pragma unroll
    for (int b = 0; b < 4; ++b)
        #pragma unroll
        for (int r = 0; r < 4; ++r) {
            float v = acc[b][r];
            #pragma unroll
            for (int off = 16; off > 0; off >>= 1)
                v += __shfl_xor_sync(0xffffffffu, v, off);
            acc[b][r] = v;
        }

    if (lane == 0) {
        #pragma unroll
        for (int r = 0; r < 4; ++r) {
            float bi = bias[n0 + r];
            #pragma unroll
            for (int b = 0; b < 4; ++b) {
                float s = acc[b][r] + bi;
                g_v[b * Nn + n0 + r] = 1.f / (1.f + expf(-s));
            }
        }
    }
}

// ---------------------------------------------------------------------------
// Kernel 3: out[b,t,f,h,w] = v[b,n] * (g3_w @ x + g3_b)[b,n,f]
// ---------------------------------------------------------------------------
__global__ void __launch_bounds__(256) out_kernel(
    const float* __restrict__ x,
    const float* __restrict__ g3_w,
    const float* __restrict__ g3_b,
    float* __restrict__ out)
{
    __shared__ float sw[Ff * Cc];
    __shared__ float sb[Ff];
    for (int i = threadIdx.x; i < Ff * Cc; i += blockDim.x) sw[i] = g3_w[i];
    if (threadIdx.x < Ff) sb[threadIdx.x] = g3_b[threadIdx.x];
    __syncthreads();

    int i  = blockIdx.x * blockDim.x + threadIdx.x;  // [0, B*N)
    int b  = i >> 13;
    int n  = i & (Nn - 1);
    int t  = n >> 10;
    int hw = n & (HW - 1);
    const float* xp = x + ((b * Tt + t) * Cc) * HW + hw;

    float acc[Ff];
    #pragma unroll
    for (int f = 0; f < Ff; ++f) acc[f] = 0.f;

    #pragma unroll 4
    for (int c = 0; c < Cc; ++c) {
        float xv = xp[c * HW];
        #pragma unroll
        for (int f = 0; f < Ff; ++f)
            acc[f] = fmaf(sw[f * Cc + c], xv, acc[f]);
    }

    float v = g_v[i];
    float* op = out + ((b * Tt + t) * Ff) * HW + hw;
    #pragma unroll
    for (int f = 0; f < Ff; ++f)
        op[f * HW] = v * (acc[f] + sb[f]);
}

// ---------------------------------------------------------------------------
extern "C" void kernel_launch(void* const* d_in, const int* in_sizes, int n_in,
                              void* d_out, int out_size)
{
    const float* x       = (const float*)d_in[0];
    // d_in[1] = x1 (unused by reference)
    const float* conv1_w = (const float*)d_in[2];
    const float* conv1_b = (const float*)d_in[3];
    const float* g3_w    = (const float*)d_in[4];
    const float* g3_b    = (const float*)d_in[5];
    const float* ffnn1_w = (const float*)d_in[6];
    const float* ffnn1_b = (const float*)d_in[7];
    float* out = (float*)d_out;

    pooled_kernel<<<BN / 256, 256>>>(x, conv1_w, conv1_b);
    gemv_kernel<<<Nn / 32, 256>>>(ffnn1_w, ffnn1_b);   // 256 blocks, 32 rows each
    out_kernel<<<BN / 256, 256>>>(x, g3_w, g3_b, out);
}

// round 4
// speedup vs baseline: 1.1492x; 1.1492x over previous
#include <cuda_runtime.h>
#include <math.h>

#define Bn 4
#define Tt 8
#define Cc 64
#define Ff 16
#define Nn 8192
#define HW 1024      // H*W
#define BN (Bn*Nn)   // 32768

typedef unsigned long long u64;

// Scratch (device globals: no allocations allowed in kernel_launch)
__device__ __align__(16) float g_pooled[BN];
__device__ __align__(16) float g_v[BN];

// ---- packed f32x2 helpers (Blackwell; ptxas never emits FFMA2 from C++) ----
__device__ __forceinline__ u64 f2fma(u64 a, u64 b, u64 c) {
    u64 d;
    asm("fma.rn.f32x2 %0, %1, %2, %3;" : "=l"(d) : "l"(a), "l"(b), "l"(c));
    return d;
}
__device__ __forceinline__ u64 f2add(u64 a, u64 b) {
    u64 d;
    asm("add.rn.f32x2 %0, %1, %2;" : "=l"(d) : "l"(a), "l"(b));
    return d;
}
__device__ __forceinline__ u64 f2mul(u64 a, u64 b) {
    u64 d;
    asm("mul.rn.f32x2 %0, %1, %2;" : "=l"(d) : "l"(a), "l"(b));
    return d;
}
__device__ __forceinline__ u64 f2pack(float lo, float hi) {
    u64 d;
    asm("mov.b64 %0, {%1, %2};" : "=l"(d) : "f"(lo), "f"(hi));
    return d;
}
__device__ __forceinline__ void f2unpack(u64 a, float& lo, float& hi) {
    asm("mov.b64 {%0, %1}, %2;" : "=f"(lo), "=f"(hi) : "l"(a));
}
__device__ __forceinline__ u64 ld64(const float* p) {   // 8B aligned caller-guaranteed
    return __double_as_longlong(*reinterpret_cast<const double*>(p));
}

// ---------------------------------------------------------------------------
// Kernel 1: pooled[b,n] = wbar . x[b,:,n] + bbar   (conv1 + avgpool collapsed)
// One thread = 2 consecutive hw (float2 loads, f32x2 math). 128 blocks x 128.
// ---------------------------------------------------------------------------
__global__ void pooled_kernel(
    const float* __restrict__ x,
    const float* __restrict__ conv1_w,
    const float* __restrict__ conv1_b)
{
    __shared__ u64 s_wbar2[Cc];   // (wbar[c], wbar[c]) packed
    __shared__ float s_bbar;
    int tid = threadIdx.x;
    if (tid < Cc) {
        float s = 0.f;
        #pragma unroll
        for (int f = 0; f < Ff; ++f) s += conv1_w[f * Cc + tid];
        s *= (1.f / Ff);
        s_wbar2[tid] = f2pack(s, s);
    }
    if (tid == Cc) {
        float s = 0.f;
        #pragma unroll
        for (int f = 0; f < Ff; ++f) s += conv1_b[f];
        s_bbar = s * (1.f / Ff);
    }
    __syncthreads();

    int i2  = blockIdx.x * blockDim.x + tid;   // [0, B*N/2)
    int b   = i2 >> 12;                        // N/2 = 4096 per batch
    int j   = i2 & 4095;
    int t   = j >> 9;                          // HW/2 = 512 per t
    int hw  = (j & 511) << 1;
    const float* xp = x + ((b * Tt + t) * Cc) * HW + hw;

    u64 a0 = 0, a1 = 0, a2 = 0, a3 = 0, a4 = 0, a5 = 0, a6 = 0, a7 = 0;
    #pragma unroll
    for (int c = 0; c < Cc; c += 8) {
        u64 x0 = ld64(xp + (c + 0) * HW);
        u64 x1 = ld64(xp + (c + 1) * HW);
        u64 x2 = ld64(xp + (c + 2) * HW);
        u64 x3 = ld64(xp + (c + 3) * HW);
        u64 x4 = ld64(xp + (c + 4) * HW);
        u64 x5 = ld64(xp + (c + 5) * HW);
        u64 x6 = ld64(xp + (c + 6) * HW);
        u64 x7 = ld64(xp + (c + 7) * HW);
        a0 = f2fma(x0, s_wbar2[c + 0], a0);
        a1 = f2fma(x1, s_wbar2[c + 1], a1);
        a2 = f2fma(x2, s_wbar2[c + 2], a2);
        a3 = f2fma(x3, s_wbar2[c + 3], a3);
        a4 = f2fma(x4, s_wbar2[c + 4], a4);
        a5 = f2fma(x5, s_wbar2[c + 5], a5);
        a6 = f2fma(x6, s_wbar2[c + 6], a6);
        a7 = f2fma(x7, s_wbar2[c + 7], a7);
    }
    u64 s01 = f2add(f2add(a0, a1), f2add(a2, a3));
    u64 s23 = f2add(f2add(a4, a5), f2add(a6, a7));
    u64 s   = f2add(s01, s23);
    float lo, hi;
    f2unpack(s, lo, hi);
    float2 r = make_float2(lo + s_bbar, hi + s_bbar);
    *reinterpret_cast<float2*>(&g_pooled[b * Nn + t * HW + hw]) = r;
}

// ---------------------------------------------------------------------------
// Kernel 2: v[b,n] = sigmoid(pooled[b,:] . W[n,:] + bias[n])
// Warp: 4 rows x 4 batches. double2 (16B) streaming loads, f32x2 FMA.
// Streams the 256MB weight matrix once -> pure HBM-bound.
// ---------------------------------------------------------------------------
__global__ void __launch_bounds__(256, 2) gemv_kernel(
    const float* __restrict__ Wm,
    const float* __restrict__ bias)
{
    int warp = threadIdx.x >> 5;
    int lane = threadIdx.x & 31;
    int n0 = (blockIdx.x * 8 + warp) * 4;   // first of 4 rows

    const double2* Wv = (const double2*)Wm;        // 1 double2 = 4 floats = 16B
    const double2* Pv = (const double2*)g_pooled;
    const int K4 = Nn / 4;                         // 2048 units per row

    u64 acc[4][4];
    #pragma unroll
    for (int b = 0; b < 4; ++b)
        #pragma unroll
        for (int r = 0; r < 4; ++r) acc[b][r] = 0ull;

    #pragma unroll 2
    for (int k4 = lane; k4 < K4; k4 += 32) {
        u64 plo[4], phi[4];
        #pragma unroll
        for (int b = 0; b < 4; ++b) {
            double2 pd = __ldg(Pv + b * K4 + k4);
            plo[b] = __double_as_longlong(pd.x);
            phi[b] = __double_as_longlong(pd.y);
        }
        #pragma unroll
        for (int r = 0; r < 4; ++r) {
            double2 wd = __ldcs(Wv + (size_t)(n0 + r) * K4 + k4);
            u64 wlo = __double_as_longlong(wd.x);
            u64 whi = __double_as_longlong(wd.y);
            #pragma unroll
            for (int b = 0; b < 4; ++b) {
                acc[b][r] = f2fma(plo[b], wlo, acc[b][r]);
                acc[b][r] = f2fma(phi[b], whi, acc[b][r]);
            }
        }
    }

    // Collapse packed lanes, then warp butterfly-reduce 16 scalars
    float red[4][4];
    #pragma unroll
    for (int b = 0; b < 4; ++b)
        #pragma unroll
        for (int r = 0; r < 4; ++r) {
            float lo, hi;
            f2unpack(acc[b][r], lo, hi);
            float v = lo + hi;
            #pragma unroll
            for (int off = 16; off > 0; off >>= 1)
                v += __shfl_xor_sync(0xffffffffu, v, off);
            red[b][r] = v;
        }

    if (lane == 0) {
        #pragma unroll
        for (int r = 0; r < 4; ++r) {
            float bi = bias[n0 + r];
            #pragma unroll
            for (int b = 0; b < 4; ++b) {
                float s = red[b][r] + bi;
                g_v[b * Nn + n0 + r] = 1.f / (1.f + __expf(-s));
            }
        }
    }
}

// ---------------------------------------------------------------------------
// Kernel 3: out[b,t,f,h,w] = v[b,n] * (g3_w @ x + g3_b)[b,n,f]
// One thread = 2 consecutive hw, f32x2 math. 128 blocks x 128 threads.
// ---------------------------------------------------------------------------
__global__ void out_kernel(
    const float* __restrict__ x,
    const float* __restrict__ g3_w,
    const float* __restrict__ g3_b,
    float* __restrict__ out)
{
    __shared__ u64 sw2[Ff * Cc];   // (w,w) packed, 8KB
    __shared__ u64 sb2[Ff];
    for (int i = threadIdx.x; i < Ff * Cc; i += blockDim.x) {
        float w = g3_w[i];
        sw2[i] = f2pack(w, w);
    }
    if (threadIdx.x < Ff) {
        float b = g3_b[threadIdx.x];
        sb2[threadIdx.x] = f2pack(b, b);
    }
    __syncthreads();

    int i2  = blockIdx.x * blockDim.x + threadIdx.x;  // [0, B*N/2)
    int b   = i2 >> 12;
    int j   = i2 & 4095;
    int t   = j >> 9;
    int hw  = (j & 511) << 1;
    const float* xp = x + ((b * Tt + t) * Cc) * HW + hw;

    u64 acc[Ff];
    #pragma unroll
    for (int f = 0; f < Ff; ++f) acc[f] = 0ull;

    #pragma unroll 8
    for (int c = 0; c < Cc; ++c) {
        u64 xv = ld64(xp + c * HW);
        #pragma unroll
        for (int f = 0; f < Ff; ++f)
            acc[f] = f2fma(xv, sw2[f * Cc + c], acc[f]);
    }

    u64 v2 = ld64(&g_v[b * Nn + t * HW + hw]);
    float* op = out + ((b * Tt + t) * Ff) * HW + hw;
    #pragma unroll
    for (int f = 0; f < Ff; ++f) {
        u64 r = f2mul(f2add(acc[f], sb2[f]), v2);
        float lo, hi;
        f2unpack(r, lo, hi);
        *reinterpret_cast<float2*>(op + f * HW) = make_float2(lo, hi);
    }
}

// ---------------------------------------------------------------------------
extern "C" void kernel_launch(void* const* d_in, const int* in_sizes, int n_in,
                              void* d_out, int out_size)
{
    const float* x       = (const float*)d_in[0];
    // d_in[1] = x1 (unused by reference)
    const float* conv1_w = (const float*)d_in[2];
    const float* conv1_b = (const float*)d_in[3];
    const float* g3_w    = (const float*)d_in[4];
    const float* g3_b    = (const float*)d_in[5];
    const float* ffnn1_w = (const float*)d_in[6];
    const float* ffnn1_b = (const float*)d_in[7];
    float* out = (float*)d_out;

    pooled_kernel<<<BN / 2 / 128, 128>>>(x, conv1_w, conv1_b);
    gemv_kernel<<<Nn / 32, 256>>>(ffnn1_w, ffnn1_b);   // 256 blocks, 32 rows each
    out_kernel<<<BN / 2 / 128, 128>>>(x, g3_w, g3_b, out);
}